// round 7
// baseline (speedup 1.0000x reference)
#include <cuda_runtime.h>
#include <cuda_bf16.h>
#include <math_constants.h>
#include <cstdint>

#define Q_LEN 2048
#define HIST  2048
#define KLEN  4096
#define NH    12
#define KVH   2
#define DH    128
#define HID   1536
#define KVDIM 256
#define GROUPS 6
#define NITEMS (NH * 16)

// Scratch (device globals: allocation-free)
// g_q : row-pair interleaved: pair p=(r>>4)*8+(r&7), half=(r>>3)&1
//       float2 q2[p*HID + col] = (row half0, row half1)
__device__ __align__(16) float g_q[Q_LEN * HID];
// g_k : per key row, within each 128-d head chunk dims permuted:
//       d=8a+u -> pos 8a + 2*(u&3) + (u>>2)   (pairs d, d+4 adjacent)
__device__ __align__(16) float g_k[KLEN * KVDIM];
// g_v : key-row-pair interleaved: pair=(k>>3)*4+(k&3), half=(k>>2)&1
//       float2 v2[pair*KVDIM + col] = (key half0, key half1)
__device__ __align__(16) float g_v[KLEN * KVDIM];
__device__ __align__(16) float g_att[Q_LEN * HID];   // plain layout
// tf32-pre-rounded copies of inputs (plain layouts)
__device__ __align__(16) float g_x[Q_LEN * HID];
__device__ __align__(16) float g_wq[HID * HID];
__device__ __align__(16) float g_wk[HID * KVDIM];
__device__ __align__(16) float g_wv[HID * KVDIM];
__device__ __align__(16) float g_wo[HID * HID];
__device__ unsigned int g_work;

// ---------------------------------------------------------------------------
// helpers
// ---------------------------------------------------------------------------
__device__ __forceinline__ float tf32r(float x) {
    uint32_t u;
    asm("cvt.rna.tf32.f32 %0, %1;" : "=r"(u) : "f"(x));
    return __uint_as_float(u);
}
__device__ __forceinline__ uint32_t fbits(float x) { return __float_as_uint(x); }
__device__ __forceinline__ int kperm(int c) {
    return (c & ~7) | ((c & 3) << 1) | ((c >> 2) & 1);
}

__device__ __forceinline__ void mma_tf32(float d[4], const uint32_t a[4],
                                         const uint32_t b[2]) {
    asm volatile(
        "mma.sync.aligned.m16n8k8.row.col.f32.tf32.tf32.f32 "
        "{%0,%1,%2,%3}, {%4,%5,%6,%7}, {%8,%9}, {%0,%1,%2,%3};\n"
        : "+f"(d[0]), "+f"(d[1]), "+f"(d[2]), "+f"(d[3])
        : "r"(a[0]), "r"(a[1]), "r"(a[2]), "r"(a[3]), "r"(b[0]), "r"(b[1]));
}

__device__ __forceinline__ void cpa16(float* dst, const float* src) {
    uint32_t d = (uint32_t)__cvta_generic_to_shared(dst);
    asm volatile("cp.async.cg.shared.global [%0], [%1], 16;\n"
                 :: "r"(d), "l"(src));
}
#define CP_COMMIT() asm volatile("cp.async.commit_group;\n")
#define CP_WAIT(n)  asm volatile("cp.async.wait_group %0;\n" :: "n"(n))

// ---------------------------------------------------------------------------
// Convert inputs to tf32-rounded copies (permuted layouts for k_hist/v_hist).
// ---------------------------------------------------------------------------
__global__ __launch_bounds__(256) void cvt_kernel(
    const float4* __restrict__ x,  const float4* __restrict__ wq,
    const float4* __restrict__ wk, const float4* __restrict__ wv,
    const float4* __restrict__ wo, const float4* __restrict__ kh,
    const float4* __restrict__ vh)
{
    if (blockIdx.x == 0 && threadIdx.x == 0) g_work = 0u;
    const int NX = Q_LEN * HID / 4, NWQ = HID * HID / 4;
    const int NWK = HID * KVDIM / 4, NWV = NWK, NWO = NWQ;
    const int NP  = NX + NWQ + NWK + NWV + NWO;
    const int NKH = HIST * KVDIM / 4, NVH = NKH;
    const int total = NP + NKH + NVH;
    int stride = gridDim.x * blockDim.x;
    for (int i = blockIdx.x * blockDim.x + threadIdx.x; i < total; i += stride) {
        if (i < NP) {
            const float4* src; float4* dst; int j = i;
            if (j < NX)                { src = x;  dst = (float4*)g_x; }
            else if ((j -= NX)  < NWQ) { src = wq; dst = (float4*)g_wq; }
            else if ((j -= NWQ) < NWK) { src = wk; dst = (float4*)g_wk; }
            else if ((j -= NWK) < NWV) { src = wv; dst = (float4*)g_wv; }
            else { j -= NWV;             src = wo; dst = (float4*)g_wo; }
            float4 v = src[j];
            dst[j] = make_float4(tf32r(v.x), tf32r(v.y), tf32r(v.z), tf32r(v.w));
        } else if (i < NP + NKH) {
            int j = i - NP;
            int r = j >> 6;               // 64 float4 per 256-col row
            int c0 = (j & 63) << 2;
            float4 v = kh[j];
            float* dst = g_k + (size_t)r * KVDIM + (c0 & ~127);
            int cc = c0 & 127;
            dst[kperm(cc)]     = tf32r(v.x);
            dst[kperm(cc + 1)] = tf32r(v.y);
            dst[kperm(cc + 2)] = tf32r(v.z);
            dst[kperm(cc + 3)] = tf32r(v.w);
        } else {
            int j = i - NP - NKH;
            int r = j >> 6;
            int c0 = (j & 63) << 2;
            float4 v = vh[j];
            int pair = ((r >> 3) << 2) | (r & 3);
            int half = (r >> 2) & 1;
            float* dst = g_v + ((size_t)pair * KVDIM + c0) * 2 + half;
            dst[0] = tf32r(v.x); dst[2] = tf32r(v.y);
            dst[4] = tf32r(v.z); dst[6] = tf32r(v.w);
        }
    }
}

// ---------------------------------------------------------------------------
// tf32 GEMM with cp.async 2-stage pipeline; epilogue modes:
//   0 = plain (+bias), 1 = Q interleaved (+bias), 2 = K perm (+bias, tf32),
//   3 = V interleaved (+bias, tf32)
// ---------------------------------------------------------------------------
#define LDA_G 36
#define LDB_G 136
#define GEMM_SMEM ((2 * 128 * LDA_G + 2 * 32 * LDB_G) * 4)

__device__ __forceinline__ void gemm_body_cp(
    const float* __restrict__ A, const float* __restrict__ B,
    const float* __restrict__ bias, float* __restrict__ C,
    int row0, int col0, int N, int K, int ldc, int mode)
{
    extern __shared__ float smg[];
    float* As = smg;
    float* Bs = smg + 2 * 128 * LDA_G;

    const int tid  = threadIdx.x;
    const int w    = tid >> 5;
    const int lane = tid & 31;
    const int g    = lane >> 2;
    const int t    = lane & 3;
    const int wm   = w >> 2;
    const int wn   = w & 3;

    float acc[16][4];
#pragma unroll
    for (int i = 0; i < 16; i++)
#pragma unroll
        for (int j = 0; j < 4; j++) acc[i][j] = 0.f;

    auto load_stage = [&](int s, int k0) {
#pragma unroll
        for (int l = 0; l < 4; l++) {
            int i = tid + l * 256;
            int r = i >> 3, c = (i & 7) << 2;
            cpa16(As + (s * 128 + r) * LDA_G + c,
                  A + (size_t)(row0 + r) * K + k0 + c);
        }
#pragma unroll
        for (int l = 0; l < 4; l++) {
            int i = tid + l * 256;
            int r = i >> 5, c = (i & 31) << 2;
            cpa16(Bs + (s * 32 + r) * LDB_G + c,
                  B + (size_t)(k0 + r) * N + col0 + c);
        }
        CP_COMMIT();
    };

    load_stage(0, 0);
    const int KT = K / 32;
    for (int kt = 0; kt < KT; kt++) {
        if (kt + 1 < KT) { load_stage((kt + 1) & 1, (kt + 1) * 32); CP_WAIT(1); }
        else             { CP_WAIT(0); }
        __syncthreads();
        const float* Ab = As + (kt & 1) * 128 * LDA_G;
        const float* Bb = Bs + (kt & 1) * 32 * LDB_G;
#pragma unroll
        for (int k8 = 0; k8 < 32; k8 += 8) {
            uint32_t a[4][4];
#pragma unroll
            for (int mi = 0; mi < 4; mi++) {
                const float* ab = Ab + (wm * 64 + mi * 16 + g) * LDA_G + k8 + t;
                a[mi][0] = fbits(ab[0]);
                a[mi][1] = fbits(ab[8 * LDA_G]);
                a[mi][2] = fbits(ab[4]);
                a[mi][3] = fbits(ab[8 * LDA_G + 4]);
            }
#pragma unroll
            for (int ni = 0; ni < 4; ni++) {
                uint32_t b[2];
                const float* bp = Bb + (k8 + t) * LDB_G + wn * 32 + ni * 8 + g;
                b[0] = fbits(bp[0]);
                b[1] = fbits(bp[4 * LDB_G]);
#pragma unroll
                for (int mi = 0; mi < 4; mi++)
                    mma_tf32(acc[mi * 4 + ni], a[mi], b);
            }
        }
        __syncthreads();
    }

#pragma unroll
    for (int mi = 0; mi < 4; mi++)
#pragma unroll
        for (int ni = 0; ni < 4; ni++) {
            int col = col0 + wn * 32 + ni * 8 + 2 * t;
            float b0 = bias ? bias[col]     : 0.f;
            float b1 = bias ? bias[col + 1] : 0.f;
            int r0 = row0 + wm * 64 + mi * 16 + g;
            float v00 = acc[mi * 4 + ni][0] + b0;
            float v01 = acc[mi * 4 + ni][1] + b1;
            float v10 = acc[mi * 4 + ni][2] + b0;
            float v11 = acc[mi * 4 + ni][3] + b1;
            if (mode == 0) {
                *(float2*)(C + (size_t)r0 * ldc + col)       = make_float2(v00, v01);
                *(float2*)(C + (size_t)(r0 + 8) * ldc + col) = make_float2(v10, v11);
            } else if (mode == 1) {
                float2* q2 = (float2*)C;
                int p = ((r0 >> 4) << 3) | (r0 & 7);
                q2[(size_t)p * HID + col]     = make_float2(v00, v10);
                q2[(size_t)p * HID + col + 1] = make_float2(v01, v11);
            } else if (mode == 2) {
                int key = HIST + r0;
                float* kb_ = C + (size_t)key * KVDIM + (col & ~127);
                int cc = col & 127;
                kb_[kperm(cc)]     = tf32r(v00);
                kb_[kperm(cc + 1)] = tf32r(v01);
                float* kb2 = kb_ + 8 * KVDIM;
                kb2[kperm(cc)]     = tf32r(v10);
                kb2[kperm(cc + 1)] = tf32r(v11);
            } else {
                int k0 = HIST + r0;
                int pair = ((k0 >> 3) << 2) | (k0 & 3);
                int half = (k0 >> 2) & 1;
                size_t b_lo = ((size_t)pair * KVDIM + col) * 2 + half;
                C[b_lo]     = tf32r(v00);
                C[b_lo + 2] = tf32r(v01);
                size_t b_hi = ((size_t)(pair + 4) * KVDIM + col) * 2 + half;
                C[b_hi]     = tf32r(v10);
                C[b_hi + 2] = tf32r(v11);
            }
        }
}

// grid.x: 0..11 -> Wq, 12..13 -> Wk, 14..15 -> Wv
__global__ __launch_bounds__(256) void gemm_qkv_kernel(
    const float* __restrict__ bq, const float* __restrict__ bk,
    const float* __restrict__ bv)
{
    int bx   = blockIdx.x;
    int row0 = blockIdx.y * 128;
    if (bx < 12) {
        gemm_body_cp(g_x, g_wq, bq, g_q, row0, bx * 128, HID, HID, HID, 1);
    } else if (bx < 14) {
        gemm_body_cp(g_x, g_wk, bk, g_k, row0, (bx - 12) * 128,
                     KVDIM, HID, KVDIM, 2);
    } else {
        gemm_body_cp(g_x, g_wv, bv, g_v, row0, (bx - 14) * 128,
                     KVDIM, HID, KVDIM, 3);
    }
}

__global__ __launch_bounds__(256) void gemm_wo_kernel(float* __restrict__ out)
{
    gemm_body_cp(g_att, g_wo, nullptr, out, blockIdx.y * 128,
                 blockIdx.x * 128, HID, HID, HID, 0);
}

// ---------------------------------------------------------------------------
// RoPE on permuted layouts.  blocks [0, 12288): Q pairs; [12288, 16384): K rows
// ---------------------------------------------------------------------------
__global__ __launch_bounds__(64) void rope_kernel(
    const float* __restrict__ fcos, const float* __restrict__ fsin)
{
    int b = blockIdx.x;
    int d = threadIdx.x;   // 0..63
    if (b < 1024 * 12) {
        int p = b / 12, h = b % 12;
        int r0 = ((p >> 3) << 4) | (p & 7);
        int r1 = r0 + 8;
        float2* q2 = (float2*)g_q;
        size_t i0 = (size_t)p * HID + h * DH + d;
        float2 xa = q2[i0];
        float2 xb = q2[i0 + 64];
        float c0 = fcos[r0 * 64 + d], s0 = fsin[r0 * 64 + d];
        float c1 = fcos[r1 * 64 + d], s1 = fsin[r1 * 64 + d];
        q2[i0]      = make_float2(tf32r(xa.x * c0 - xb.x * s0),
                                  tf32r(xa.y * c1 - xb.y * s1));
        q2[i0 + 64] = make_float2(tf32r(xa.x * s0 + xb.x * c0),
                                  tf32r(xa.y * s1 + xb.y * c1));
    } else {
        b -= 1024 * 12;
        int r = b >> 1, kvh = b & 1;
        float* base = g_k + (size_t)(HIST + r) * KVDIM + kvh * DH;
        int i1 = kperm(d), i2 = kperm(d + 64);
        float x1 = base[i1], x2 = base[i2];
        float c = fcos[r * 64 + d], s = fsin[r * 64 + d];
        base[i1] = tf32r(x1 * c - x2 * s);
        base[i2] = tf32r(x1 * s + x2 * c);
    }
}

// ---------------------------------------------------------------------------
// Persistent flash attention, tf32 mma, vectorized fragments, cp.async.
// ---------------------------------------------------------------------------
#define QSTR 264   // floats per Q pair-row (128 float2 + pad)
#define KSTR 136   // floats per K key-row
#define VSTR 272   // floats per V pair-row
#define PSTR 136   // floats per P pair-row
#define AQ_F (64 * QSTR)
#define AK_F (2 * 64 * KSTR)
#define AV_F (32 * VSTR)
#define AP_F (8 * 8 * PSTR)
#define AW_OFF (AQ_F + AK_F + AV_F + AP_F)
#define ATTN_SMEM ((AW_OFF + 4) * 4)

__global__ __launch_bounds__(256) void attn_kernel()
{
    extern __shared__ float sm[];
    float* Qs = sm;                      // [64 pairs][QSTR]
    float* Ks = sm + AQ_F;               // 2 stages [64 keys][KSTR]
    float* Vs = sm + AQ_F + AK_F;        // [32 pairs][VSTR]
    float* Ps = sm + AQ_F + AK_F + AV_F; // [8 warps][8 pairs][PSTR]
    int* widx = (int*)(sm + AW_OFF);

    const int tid  = threadIdx.x;
    const int w    = tid >> 5;
    const int lane = tid & 31;
    const int g    = lane >> 2;
    const int t    = lane & 3;
    const float SC = 0.12751689932560563f;  // 1/sqrt(128) * log2(e)
    float* Pw = Ps + w * 8 * PSTR;

    for (;;) {
        if (tid == 0) *widx = (int)atomicAdd(&g_work, 1u);
        __syncthreads();
        const int item = *widx;
        if (item >= NITEMS) break;
        const int qt   = 15 - item / NH;     // descending nkt (LPT)
        const int head = item % NH;
        const int q0   = qt * 128;
        const int kvh  = head / GROUPS;

        // Q tile: 64 pair-rows x 256 floats
#pragma unroll
        for (int l = 0; l < 16; l++) {
            int i = tid + l * 256;
            int pr = i >> 6, ch = i & 63;
            cpa16(Qs + pr * QSTR + ch * 4,
                  g_q + ((size_t)(q0 / 2 + pr) * HID + head * DH) * 2 + ch * 4);
        }
        CP_COMMIT();
        // K(0) into stage 0
#pragma unroll
        for (int l = 0; l < 8; l++) {
            int i = tid + l * 256;
            int r = i >> 5, ch = i & 31;
            cpa16(Ks + r * KSTR + ch * 4,
                  g_k + (size_t)r * KVDIM + kvh * DH + ch * 4);
        }
        CP_COMMIT();

        float o[16][4];
#pragma unroll
        for (int i = 0; i < 16; i++)
#pragma unroll
            for (int j = 0; j < 4; j++) o[i][j] = 0.f;
        float m0 = -1e30f, m1 = -1e30f, l0 = 0.f, l1 = 0.f;
        const int row0g = q0 + w * 16 + g;
        const int nkt = (q0 + 128 + HIST) / 64;

        for (int kt = 0; kt < nkt; kt++) {
            const int kb = kt * 64;
            const float* Kcur = Ks + (kt & 1) * 64 * KSTR;
            const bool more = (kt + 1 < nkt);

            // issue V(kt): 32 pair-rows x 256 floats
#pragma unroll
            for (int l = 0; l < 8; l++) {
                int i = tid + l * 256;
                int pr = i >> 6, ch = i & 63;
                cpa16(Vs + pr * VSTR + ch * 4,
                      g_v + ((size_t)(kb / 2 + pr) * KVDIM + kvh * DH) * 2 + ch * 4);
            }
            CP_COMMIT();
            // issue K(kt+1)
            if (more) {
                float* Knx = Ks + ((kt + 1) & 1) * 64 * KSTR;
#pragma unroll
                for (int l = 0; l < 8; l++) {
                    int i = tid + l * 256;
                    int r = i >> 5, ch = i & 31;
                    cpa16(Knx + r * KSTR + ch * 4,
                          g_k + (size_t)(kb + 64 + r) * KVDIM + kvh * DH + ch * 4);
                }
                CP_COMMIT();
                CP_WAIT(2);
            } else {
                CP_WAIT(1);
            }
            __syncthreads();

            // S = Q K^T  (all fragment loads 64-bit)
            float s[8][4];
#pragma unroll
            for (int j = 0; j < 8; j++)
#pragma unroll
                for (int e = 0; e < 4; e++) s[j][e] = 0.f;
#pragma unroll
            for (int k8 = 0; k8 < 128; k8 += 8) {
                float2 qa0 = *(const float2*)(Qs + (w * 8 + g) * QSTR + 2 * (k8 + t));
                float2 qa1 = *(const float2*)(Qs + (w * 8 + g) * QSTR + 2 * (k8 + t + 4));
                uint32_t a[4] = {fbits(qa0.x), fbits(qa0.y),
                                 fbits(qa1.x), fbits(qa1.y)};
#pragma unroll
                for (int j = 0; j < 8; j++) {
                    float2 kb2 = *(const float2*)(Kcur + (j * 8 + g) * KSTR + k8 + 2 * t);
                    uint32_t b2[2] = {fbits(kb2.x), fbits(kb2.y)};
                    mma_tf32(s[j], a, b2);
                }
            }

            // scale + (rare) causal mask
            if (kb + 63 > q0 + HIST) {
#pragma unroll
                for (int j = 0; j < 8; j++) {
                    int colg = kb + j * 8 + 2 * t;
                    s[j][0] = (colg     <= row0g + HIST)     ? s[j][0] * SC : -1e30f;
                    s[j][1] = (colg + 1 <= row0g + HIST)     ? s[j][1] * SC : -1e30f;
                    s[j][2] = (colg     <= row0g + 8 + HIST) ? s[j][2] * SC : -1e30f;
                    s[j][3] = (colg + 1 <= row0g + 8 + HIST) ? s[j][3] * SC : -1e30f;
                }
            } else {
#pragma unroll
                for (int j = 0; j < 8; j++) {
                    s[j][0] *= SC; s[j][1] *= SC;
                    s[j][2] *= SC; s[j][3] *= SC;
                }
            }

            // online softmax (quad reduce)
            float mx0 = -1e30f, mx1 = -1e30f;
#pragma unroll
            for (int j = 0; j < 8; j++) {
                mx0 = fmaxf(mx0, fmaxf(s[j][0], s[j][1]));
                mx1 = fmaxf(mx1, fmaxf(s[j][2], s[j][3]));
            }
            mx0 = fmaxf(mx0, __shfl_xor_sync(0xffffffffu, mx0, 1));
            mx0 = fmaxf(mx0, __shfl_xor_sync(0xffffffffu, mx0, 2));
            mx1 = fmaxf(mx1, __shfl_xor_sync(0xffffffffu, mx1, 1));
            mx1 = fmaxf(mx1, __shfl_xor_sync(0xffffffffu, mx1, 2));
            float mn0 = fmaxf(m0, mx0), mn1 = fmaxf(m1, mx1);
            float c0 = exp2f(m0 - mn0), c1 = exp2f(m1 - mn1);
            m0 = mn0; m1 = mn1;
            float sum0 = 0.f, sum1 = 0.f;
#pragma unroll
            for (int j = 0; j < 8; j++) {
                s[j][0] = exp2f(s[j][0] - m0);
                s[j][1] = exp2f(s[j][1] - m0);
                s[j][2] = exp2f(s[j][2] - m1);
                s[j][3] = exp2f(s[j][3] - m1);
                sum0 += s[j][0] + s[j][1];
                sum1 += s[j][2] + s[j][3];
            }
            sum0 += __shfl_xor_sync(0xffffffffu, sum0, 1);
            sum0 += __shfl_xor_sync(0xffffffffu, sum0, 2);
            sum1 += __shfl_xor_sync(0xffffffffu, sum1, 1);
            sum1 += __shfl_xor_sync(0xffffffffu, sum1, 2);
            l0 = l0 * c0 + sum0;
            l1 = l1 * c1 + sum1;

#pragma unroll
            for (int j = 0; j < 16; j++) {
                o[j][0] *= c0; o[j][1] *= c0;
                o[j][2] *= c1; o[j][3] *= c1;
            }

            // stage P interleaved: Pw[g][u] = (P[row g][u], P[row g+8][u])
#pragma unroll
            for (int j = 0; j < 8; j++) {
                *(float2*)(Pw + g * PSTR + 2 * (8 * j + 2 * t)) =
                    make_float2(tf32r(s[j][0]), tf32r(s[j][2]));
                *(float2*)(Pw + g * PSTR + 2 * (8 * j + 2 * t + 1)) =
                    make_float2(tf32r(s[j][1]), tf32r(s[j][3]));
            }
            __syncwarp();

            if (more) { CP_WAIT(1); } else { CP_WAIT(0); }   // V(kt) done
            __syncthreads();

            // O += P @ V  (vectorized fragments)
#pragma unroll
            for (int k8 = 0; k8 < 64; k8 += 8) {
                float2 pa0 = *(const float2*)(Pw + g * PSTR + 2 * (k8 + t));
                float2 pa1 = *(const float2*)(Pw + g * PSTR + 2 * (k8 + t + 4));
                uint32_t a[4] = {fbits(pa0.x), fbits(pa0.y),
                                 fbits(pa1.x), fbits(pa1.y)};
#pragma unroll
                for (int j = 0; j < 16; j++) {
                    float2 vb2 = *(const float2*)(Vs + ((k8 >> 3) * 4 + t) * VSTR
                                                  + 2 * (j * 8 + g));
                    uint32_t b2[2] = {fbits(vb2.x), fbits(vb2.y)};
                    mma_tf32(o[j], a, b2);
                }
            }
            __syncthreads();
        }

        // normalize + store (plain layout, tf32-rounded for Wo GEMM)
        float inv0 = 1.f / l0, inv1 = 1.f / l1;
#pragma unroll
        for (int j = 0; j < 16; j++) {
            float* a0 = g_att + (size_t)row0g * HID + head * DH + j * 8 + 2 * t;
            float* a1 = a0 + 8 * HID;
            *(float2*)a0 = make_float2(tf32r(o[j][0] * inv0),
                                       tf32r(o[j][1] * inv0));
            *(float2*)a1 = make_float2(tf32r(o[j][2] * inv1),
                                       tf32r(o[j][3] * inv1));
        }
        __syncthreads();
    }
}

// ---------------------------------------------------------------------------
extern "C" void kernel_launch(void* const* d_in, const int* in_sizes, int n_in,
                              void* d_out, int out_size)
{
    const float* x      = (const float*)d_in[0];
    const float* Wq     = (const float*)d_in[1];
    const float* bq     = (const float*)d_in[2];
    const float* Wk     = (const float*)d_in[3];
    const float* bk     = (const float*)d_in[4];
    const float* Wv     = (const float*)d_in[5];
    const float* bv     = (const float*)d_in[6];
    const float* Wo     = (const float*)d_in[7];
    const float* k_hist = (const float*)d_in[8];
    const float* v_hist = (const float*)d_in[9];
    const float* fcos   = (const float*)d_in[10];
    const float* fsin   = (const float*)d_in[11];
    float* out = (float*)d_out;

    cudaFuncSetAttribute(attn_kernel,
                         cudaFuncAttributeMaxDynamicSharedMemorySize, ATTN_SMEM);
    cudaFuncSetAttribute(gemm_qkv_kernel,
                         cudaFuncAttributeMaxDynamicSharedMemorySize, GEMM_SMEM);
    cudaFuncSetAttribute(gemm_wo_kernel,
                         cudaFuncAttributeMaxDynamicSharedMemorySize, GEMM_SMEM);

    // pre-round inputs to tf32 (permuted K/V history), reset work queue
    cvt_kernel<<<2368, 256>>>((const float4*)x, (const float4*)Wq,
                              (const float4*)Wk, (const float4*)Wv,
                              (const float4*)Wo, (const float4*)k_hist,
                              (const float4*)v_hist);

    // fused QKV projection (permuted epilogues)
    gemm_qkv_kernel<<<dim3(16, 16), 256, GEMM_SMEM>>>(bq, bk, bv);

    // RoPE (permuted layouts)
    rope_kernel<<<1024 * 12 + 2048 * 2, 64>>>(fcos, fsin);

    // attention (persistent, work-queue balanced, vectorized fragments)
    attn_kernel<<<148, 256, ATTN_SMEM>>>();

    // output projection
    gemm_wo_kernel<<<dim3(HID / 128, Q_LEN / 128), 256, GEMM_SMEM>>>(out);
}

// round 8
// speedup vs baseline: 1.7400x; 1.7400x over previous
#include <cuda_runtime.h>
#include <cuda_bf16.h>
#include <math_constants.h>
#include <cstdint>

#define Q_LEN 2048
#define HIST  2048
#define KLEN  4096
#define NH    12
#define KVH   2
#define DH    128
#define HID   1536
#define KVDIM 256
#define GROUPS 6
#define NITEMS (NH * 16)

// Scratch (device globals: allocation-free)
__device__ __align__(16) float g_q[Q_LEN * HID];
__device__ __align__(16) float g_k[KLEN * KVDIM];
__device__ __align__(16) float g_v[KLEN * KVDIM];
__device__ __align__(16) float g_att[Q_LEN * HID];
// tf32-pre-rounded copies of inputs
__device__ __align__(16) float g_x[Q_LEN * HID];
__device__ __align__(16) float g_wq[HID * HID];
__device__ __align__(16) float g_wk[HID * KVDIM];
__device__ __align__(16) float g_wv[HID * KVDIM];
__device__ __align__(16) float g_wo[HID * HID];
__device__ unsigned int g_work;

// ---------------------------------------------------------------------------
// helpers
// ---------------------------------------------------------------------------
__device__ __forceinline__ float tf32r(float x) {
    uint32_t u;
    asm("cvt.rna.tf32.f32 %0, %1;" : "=r"(u) : "f"(x));
    return __uint_as_float(u);
}
__device__ __forceinline__ uint32_t fbits(float x) { return __float_as_uint(x); }

__device__ __forceinline__ void mma_tf32(float d[4], const uint32_t a[4],
                                         const uint32_t b[2]) {
    asm volatile(
        "mma.sync.aligned.m16n8k8.row.col.f32.tf32.tf32.f32 "
        "{%0,%1,%2,%3}, {%4,%5,%6,%7}, {%8,%9}, {%0,%1,%2,%3};\n"
        : "+f"(d[0]), "+f"(d[1]), "+f"(d[2]), "+f"(d[3])
        : "r"(a[0]), "r"(a[1]), "r"(a[2]), "r"(a[3]), "r"(b[0]), "r"(b[1]));
}

__device__ __forceinline__ void cpa16(float* dst, const float* src) {
    uint32_t d = (uint32_t)__cvta_generic_to_shared(dst);
    asm volatile("cp.async.cg.shared.global [%0], [%1], 16;\n"
                 :: "r"(d), "l"(src));
}
#define CP_COMMIT() asm volatile("cp.async.commit_group;\n")
#define CP_WAIT(n)  asm volatile("cp.async.wait_group %0;\n" :: "n"(n))

// ---------------------------------------------------------------------------
// Convert inputs to tf32-rounded copies; reset work counter; fill K/V history.
// ---------------------------------------------------------------------------
__global__ __launch_bounds__(256) void cvt_kernel(
    const float4* __restrict__ x,  const float4* __restrict__ wq,
    const float4* __restrict__ wk, const float4* __restrict__ wv,
    const float4* __restrict__ wo, const float4* __restrict__ kh,
    const float4* __restrict__ vh)
{
    if (blockIdx.x == 0 && threadIdx.x == 0) g_work = 0u;
    const int NX = Q_LEN * HID / 4, NWQ = HID * HID / 4;
    const int NWK = HID * KVDIM / 4, NWV = NWK, NWO = NWQ;
    const int NKH = HIST * KVDIM / 4, NVH = NKH;
    const int total = NX + NWQ + NWK + NWV + NWO + NKH + NVH;
    int stride = gridDim.x * blockDim.x;
    for (int i = blockIdx.x * blockDim.x + threadIdx.x; i < total; i += stride) {
        const float4* src; float4* dst; int j = i;
        if (j < NX)            { src = x;  dst = (float4*)g_x; }
        else if ((j -= NX)  < NWQ) { src = wq; dst = (float4*)g_wq; }
        else if ((j -= NWQ) < NWK) { src = wk; dst = (float4*)g_wk; }
        else if ((j -= NWK) < NWV) { src = wv; dst = (float4*)g_wv; }
        else if ((j -= NWV) < NWO) { src = wo; dst = (float4*)g_wo; }
        else if ((j -= NWO) < NKH) { src = kh; dst = (float4*)g_k; }
        else { j -= NKH;             src = vh; dst = (float4*)g_v; }
        float4 v = src[j];
        dst[j] = make_float4(tf32r(v.x), tf32r(v.y), tf32r(v.z), tf32r(v.w));
    }
}

// ---------------------------------------------------------------------------
// tf32 GEMM with cp.async 2-stage pipeline.
// C[row0..+128, col0..+128] = A[M,K]@B[K,N] (+bias). 8 warps 2x4, warp 64x32.
// ---------------------------------------------------------------------------
#define LDA_G 36
#define LDB_G 136
#define GEMM_SMEM ((2 * 128 * LDA_G + 2 * 32 * LDB_G) * 4)

__device__ __forceinline__ void gemm_body_cp(
    const float* __restrict__ A, const float* __restrict__ B,
    const float* __restrict__ bias, float* __restrict__ C,
    int row0, int col0, int N, int K, int ldc, bool round_out)
{
    extern __shared__ float smg[];
    float* As = smg;
    float* Bs = smg + 2 * 128 * LDA_G;

    const int tid  = threadIdx.x;
    const int w    = tid >> 5;
    const int lane = tid & 31;
    const int g    = lane >> 2;
    const int t    = lane & 3;
    const int wm   = w >> 2;
    const int wn   = w & 3;

    float acc[16][4];
#pragma unroll
    for (int i = 0; i < 16; i++)
#pragma unroll
        for (int j = 0; j < 4; j++) acc[i][j] = 0.f;

    auto load_stage = [&](int s, int k0) {
#pragma unroll
        for (int l = 0; l < 4; l++) {
            int i = tid + l * 256;
            int r = i >> 3, c = (i & 7) << 2;
            cpa16(As + (s * 128 + r) * LDA_G + c,
                  A + (size_t)(row0 + r) * K + k0 + c);
        }
#pragma unroll
        for (int l = 0; l < 4; l++) {
            int i = tid + l * 256;
            int r = i >> 5, c = (i & 31) << 2;
            cpa16(Bs + (s * 32 + r) * LDB_G + c,
                  B + (size_t)(k0 + r) * N + col0 + c);
        }
        CP_COMMIT();
    };

    load_stage(0, 0);
    const int KT = K / 32;
    for (int kt = 0; kt < KT; kt++) {
        if (kt + 1 < KT) { load_stage((kt + 1) & 1, (kt + 1) * 32); CP_WAIT(1); }
        else             { CP_WAIT(0); }
        __syncthreads();
        const float* Ab = As + (kt & 1) * 128 * LDA_G;
        const float* Bb = Bs + (kt & 1) * 32 * LDB_G;
#pragma unroll
        for (int k8 = 0; k8 < 32; k8 += 8) {
            uint32_t a[4][4];
#pragma unroll
            for (int mi = 0; mi < 4; mi++) {
                const float* ab = Ab + (wm * 64 + mi * 16 + g) * LDA_G + k8 + t;
                a[mi][0] = fbits(ab[0]);
                a[mi][1] = fbits(ab[8 * LDA_G]);
                a[mi][2] = fbits(ab[4]);
                a[mi][3] = fbits(ab[8 * LDA_G + 4]);
            }
#pragma unroll
            for (int ni = 0; ni < 4; ni++) {
                uint32_t b[2];
                const float* bp = Bb + (k8 + t) * LDB_G + wn * 32 + ni * 8 + g;
                b[0] = fbits(bp[0]);
                b[1] = fbits(bp[4 * LDB_G]);
#pragma unroll
                for (int mi = 0; mi < 4; mi++)
                    mma_tf32(acc[mi * 4 + ni], a[mi], b);
            }
        }
        __syncthreads();
    }

#pragma unroll
    for (int mi = 0; mi < 4; mi++)
#pragma unroll
        for (int ni = 0; ni < 4; ni++) {
            int col = col0 + wn * 32 + ni * 8 + 2 * t;
            float b0 = bias ? bias[col]     : 0.f;
            float b1 = bias ? bias[col + 1] : 0.f;
            int r0 = row0 + wm * 64 + mi * 16 + g;
            float v00 = acc[mi * 4 + ni][0] + b0;
            float v01 = acc[mi * 4 + ni][1] + b1;
            float v10 = acc[mi * 4 + ni][2] + b0;
            float v11 = acc[mi * 4 + ni][3] + b1;
            if (round_out) {
                v00 = tf32r(v00); v01 = tf32r(v01);
                v10 = tf32r(v10); v11 = tf32r(v11);
            }
            *(float2*)(C + (size_t)r0 * ldc + col)       = make_float2(v00, v01);
            *(float2*)(C + (size_t)(r0 + 8) * ldc + col) = make_float2(v10, v11);
        }
}

// grid.x: 0..11 -> Wq, 12..13 -> Wk, 14..15 -> Wv
__global__ __launch_bounds__(256) void gemm_qkv_kernel(
    const float* __restrict__ bq, const float* __restrict__ bk,
    const float* __restrict__ bv)
{
    int bx   = blockIdx.x;
    int row0 = blockIdx.y * 128;
    if (bx < 12) {
        gemm_body_cp(g_x, g_wq, bq, g_q, row0, bx * 128, HID, HID, HID, false);
    } else if (bx < 14) {
        gemm_body_cp(g_x, g_wk, bk, g_k + (size_t)HIST * KVDIM, row0,
                     (bx - 12) * 128, KVDIM, HID, KVDIM, true);
    } else {
        gemm_body_cp(g_x, g_wv, bv, g_v + (size_t)HIST * KVDIM, row0,
                     (bx - 14) * 128, KVDIM, HID, KVDIM, true);
    }
}

__global__ __launch_bounds__(256) void gemm_wo_kernel(float* __restrict__ out)
{
    gemm_body_cp(g_att, g_wo, nullptr, out, blockIdx.y * 128,
                 blockIdx.x * 128, HID, HID, HID, false);
}

// ---------------------------------------------------------------------------
// RoPE (writes tf32-rounded)
// ---------------------------------------------------------------------------
__global__ __launch_bounds__(64) void rope_kernel(
    const float* __restrict__ fcos, const float* __restrict__ fsin)
{
    int b  = blockIdx.x;
    int t  = b / 14;
    int hh = b % 14;
    int d  = threadIdx.x;   // 0..63
    float c = fcos[t * 64 + d];
    float s = fsin[t * 64 + d];
    float* base;
    if (hh < 12) base = g_q + (size_t)t * HID + hh * DH;
    else         base = g_k + (size_t)(HIST + t) * KVDIM + (hh - 12) * DH;
    float x1 = base[d];
    float x2 = base[d + 64];
    base[d]      = tf32r(x1 * c - x2 * s);
    base[d + 64] = tf32r(x1 * s + x2 * c);
}

// ---------------------------------------------------------------------------
// Persistent flash attention, tf32 mma, cp.async pipelined.
// Q fragments held in registers per work item; K double-buffered; V
// single-buffered (load overlapped behind S phase).
// ---------------------------------------------------------------------------
#define LDQ 132
#define LDK 132
#define LDV 136
#define LDP 68
#define AK_OFF (128 * LDQ)
#define AV_OFF (AK_OFF + 2 * 64 * LDK)
#define AP_OFF (AV_OFF + 64 * LDV)
#define AW_OFF (AP_OFF + 128 * LDP)
#define ATTN_SMEM ((AW_OFF + 4) * 4)

__global__ __launch_bounds__(256) void attn_kernel()
{
    extern __shared__ float sm[];
    float* Qs = sm;
    float* Ks = sm + AK_OFF;
    float* Vs = sm + AV_OFF;
    float* Ps = sm + AP_OFF;
    int* widx = (int*)(sm + AW_OFF);

    const int tid  = threadIdx.x;
    const int w    = tid >> 5;
    const int lane = tid & 31;
    const int g    = lane >> 2;
    const int t    = lane & 3;
    const float SC = 0.12751689932560563f;  // 1/sqrt(128) * log2(e)

    for (;;) {
        if (tid == 0) *widx = (int)atomicAdd(&g_work, 1u);
        __syncthreads();
        const int item = *widx;
        if (item >= NITEMS) break;
        const int qt   = 15 - item / NH;     // descending nkt (LPT)
        const int head = item % NH;
        const int q0   = qt * 128;
        const int kvh  = head / GROUPS;

        // Q tile -> smem (staging for register fragments)
#pragma unroll
        for (int l = 0; l < 16; l++) {
            int i = tid + l * 256;
            int r = i >> 5, c = (i & 31) << 2;
            cpa16(Qs + r * LDQ + c, g_q + (size_t)(q0 + r) * HID + head * DH + c);
        }
        CP_COMMIT();
        // K(0) into stage 0
#pragma unroll
        for (int l = 0; l < 8; l++) {
            int i = tid + l * 256;
            int r = i >> 5, c = (i & 31) << 2;
            cpa16(Ks + r * LDK + c, g_k + (size_t)r * KVDIM + kvh * DH + c);
        }
        CP_COMMIT();

        // retire Q (K0 may still be in flight), capture Q fragments to regs
        CP_WAIT(1);
        __syncthreads();
        uint32_t qf[16][4];
#pragma unroll
        for (int k8g = 0; k8g < 16; k8g++) {
            const float* qb = Qs + (w * 16 + g) * LDQ + k8g * 8 + t;
            qf[k8g][0] = fbits(qb[0]);
            qf[k8g][1] = fbits(qb[8 * LDQ]);
            qf[k8g][2] = fbits(qb[4]);
            qf[k8g][3] = fbits(qb[8 * LDQ + 4]);
        }

        float o[16][4];
#pragma unroll
        for (int i = 0; i < 16; i++)
#pragma unroll
            for (int j = 0; j < 4; j++) o[i][j] = 0.f;
        float m0 = -1e30f, m1 = -1e30f, l0 = 0.f, l1 = 0.f;
        const int row0g = q0 + w * 16 + g;
        const int nkt = (q0 + 128 + HIST) / 64;

        for (int kt = 0; kt < nkt; kt++) {
            const int kb = kt * 64;
            const float* Kcur = Ks + (kt & 1) * 64 * LDK;
            const bool more = (kt + 1 < nkt);

            // issue V(kt)
#pragma unroll
            for (int l = 0; l < 8; l++) {
                int i = tid + l * 256;
                int r = i >> 5, c = (i & 31) << 2;
                cpa16(Vs + r * LDV + c,
                      g_v + (size_t)(kb + r) * KVDIM + kvh * DH + c);
            }
            CP_COMMIT();
            // issue K(kt+1)
            if (more) {
                float* Knx = Ks + ((kt + 1) & 1) * 64 * LDK;
#pragma unroll
                for (int l = 0; l < 8; l++) {
                    int i = tid + l * 256;
                    int r = i >> 5, c = (i & 31) << 2;
                    cpa16(Knx + r * LDK + c,
                          g_k + (size_t)(kb + 64 + r) * KVDIM + kvh * DH + c);
                }
                CP_COMMIT();
                CP_WAIT(2);          // K(kt) done
            } else {
                CP_WAIT(1);
            }
            __syncthreads();

            // S = Q K^T  (Q fragments from registers)
            float s[8][4];
#pragma unroll
            for (int j = 0; j < 8; j++)
#pragma unroll
                for (int e = 0; e < 4; e++) s[j][e] = 0.f;
#pragma unroll
            for (int k8 = 0; k8 < 128; k8 += 8) {
#pragma unroll
                for (int j = 0; j < 8; j++) {
                    uint32_t b[2];
                    const float* kp = Kcur + (j * 8 + g) * LDK + k8 + t;
                    b[0] = fbits(kp[0]);
                    b[1] = fbits(kp[4]);
                    mma_tf32(s[j], qf[k8 >> 3], b);
                }
            }

            // scale + (rare) causal mask
            if (kb + 63 > q0 + HIST) {
#pragma unroll
                for (int j = 0; j < 8; j++) {
                    int colg = kb + j * 8 + 2 * t;
                    s[j][0] = (colg     <= row0g + HIST)     ? s[j][0] * SC : -1e30f;
                    s[j][1] = (colg + 1 <= row0g + HIST)     ? s[j][1] * SC : -1e30f;
                    s[j][2] = (colg     <= row0g + 8 + HIST) ? s[j][2] * SC : -1e30f;
                    s[j][3] = (colg + 1 <= row0g + 8 + HIST) ? s[j][3] * SC : -1e30f;
                }
            } else {
#pragma unroll
                for (int j = 0; j < 8; j++) {
                    s[j][0] *= SC; s[j][1] *= SC;
                    s[j][2] *= SC; s[j][3] *= SC;
                }
            }

            // online softmax (quad reduce)
            float mx0 = -1e30f, mx1 = -1e30f;
#pragma unroll
            for (int j = 0; j < 8; j++) {
                mx0 = fmaxf(mx0, fmaxf(s[j][0], s[j][1]));
                mx1 = fmaxf(mx1, fmaxf(s[j][2], s[j][3]));
            }
            mx0 = fmaxf(mx0, __shfl_xor_sync(0xffffffffu, mx0, 1));
            mx0 = fmaxf(mx0, __shfl_xor_sync(0xffffffffu, mx0, 2));
            mx1 = fmaxf(mx1, __shfl_xor_sync(0xffffffffu, mx1, 1));
            mx1 = fmaxf(mx1, __shfl_xor_sync(0xffffffffu, mx1, 2));
            float mn0 = fmaxf(m0, mx0), mn1 = fmaxf(m1, mx1);
            float c0 = exp2f(m0 - mn0), c1 = exp2f(m1 - mn1);
            m0 = mn0; m1 = mn1;
            float sum0 = 0.f, sum1 = 0.f;
#pragma unroll
            for (int j = 0; j < 8; j++) {
                s[j][0] = exp2f(s[j][0] - m0);
                s[j][1] = exp2f(s[j][1] - m0);
                s[j][2] = exp2f(s[j][2] - m1);
                s[j][3] = exp2f(s[j][3] - m1);
                sum0 += s[j][0] + s[j][1];
                sum1 += s[j][2] + s[j][3];
            }
            sum0 += __shfl_xor_sync(0xffffffffu, sum0, 1);
            sum0 += __shfl_xor_sync(0xffffffffu, sum0, 2);
            sum1 += __shfl_xor_sync(0xffffffffu, sum1, 1);
            sum1 += __shfl_xor_sync(0xffffffffu, sum1, 2);
            l0 = l0 * c0 + sum0;
            l1 = l1 * c1 + sum1;

#pragma unroll
            for (int j = 0; j < 16; j++) {
                o[j][0] *= c0; o[j][1] *= c0;
                o[j][2] *= c1; o[j][3] *= c1;
            }

            // stage P (tf32) in warp-private slab
            {
                float* p0 = Ps + (w * 16 + g) * LDP;
                float* p1 = p0 + 8 * LDP;
#pragma unroll
                for (int j = 0; j < 8; j++) {
                    *(float2*)(p0 + j * 8 + 2 * t) =
                        make_float2(tf32r(s[j][0]), tf32r(s[j][1]));
                    *(float2*)(p1 + j * 8 + 2 * t) =
                        make_float2(tf32r(s[j][2]), tf32r(s[j][3]));
                }
            }
            __syncwarp();

            if (more) { CP_WAIT(1); } else { CP_WAIT(0); }   // V(kt) done
            __syncthreads();

            // O += P @ V
#pragma unroll
            for (int k8 = 0; k8 < 64; k8 += 8) {
                uint32_t a[4];
                const float* pb = Ps + (w * 16 + g) * LDP + k8 + t;
                a[0] = fbits(pb[0]);
                a[1] = fbits(pb[8 * LDP]);
                a[2] = fbits(pb[4]);
                a[3] = fbits(pb[8 * LDP + 4]);
#pragma unroll
                for (int j = 0; j < 16; j++) {
                    uint32_t b[2];
                    const float* vb = Vs + (k8 + t) * LDV + j * 8 + g;
                    b[0] = fbits(vb[0]);
                    b[1] = fbits(vb[4 * LDV]);
                    mma_tf32(o[j], a, b);
                }
            }
            __syncthreads();
        }

        // normalize + store (tf32-rounded: feeds Wo GEMM)
        float inv0 = 1.f / l0, inv1 = 1.f / l1;
#pragma unroll
        for (int j = 0; j < 16; j++) {
            float* a0 = g_att + (size_t)row0g * HID + head * DH + j * 8 + 2 * t;
            float* a1 = a0 + 8 * HID;
            *(float2*)a0 = make_float2(tf32r(o[j][0] * inv0),
                                       tf32r(o[j][1] * inv0));
            *(float2*)a1 = make_float2(tf32r(o[j][2] * inv1),
                                       tf32r(o[j][3] * inv1));
        }
        __syncthreads();
    }
}

// ---------------------------------------------------------------------------
extern "C" void kernel_launch(void* const* d_in, const int* in_sizes, int n_in,
                              void* d_out, int out_size)
{
    const float* x      = (const float*)d_in[0];
    const float* Wq     = (const float*)d_in[1];
    const float* bq     = (const float*)d_in[2];
    const float* Wk     = (const float*)d_in[3];
    const float* bk     = (const float*)d_in[4];
    const float* Wv     = (const float*)d_in[5];
    const float* bv     = (const float*)d_in[6];
    const float* Wo     = (const float*)d_in[7];
    const float* k_hist = (const float*)d_in[8];
    const float* v_hist = (const float*)d_in[9];
    const float* fcos   = (const float*)d_in[10];
    const float* fsin   = (const float*)d_in[11];
    float* out = (float*)d_out;

    cudaFuncSetAttribute(attn_kernel,
                         cudaFuncAttributeMaxDynamicSharedMemorySize, ATTN_SMEM);
    cudaFuncSetAttribute(gemm_qkv_kernel,
                         cudaFuncAttributeMaxDynamicSharedMemorySize, GEMM_SMEM);
    cudaFuncSetAttribute(gemm_wo_kernel,
                         cudaFuncAttributeMaxDynamicSharedMemorySize, GEMM_SMEM);

    // pre-round inputs to tf32, fill K/V history, reset work queue
    cvt_kernel<<<2368, 256>>>((const float4*)x, (const float4*)Wq,
                              (const float4*)Wk, (const float4*)Wv,
                              (const float4*)Wo, (const float4*)k_hist,
                              (const float4*)v_hist);

    // fused QKV projection
    gemm_qkv_kernel<<<dim3(16, 16), 256, GEMM_SMEM>>>(bq, bk, bv);

    // RoPE
    rope_kernel<<<Q_LEN * 14, 64>>>(fcos, fsin);

    // attention (persistent, work-queue balanced, Q frags in registers)
    attn_kernel<<<148, 256, ATTN_SMEM>>>();

    // output projection
    gemm_wo_kernel<<<dim3(HID / 128, Q_LEN / 128), 256, GEMM_SMEM>>>(out);
}

// round 9
// speedup vs baseline: 2.5089x; 1.4419x over previous
#include <cuda_runtime.h>
#include <cuda_fp16.h>
#include <math_constants.h>
#include <cstdint>

#define Q_LEN 2048
#define HIST  2048
#define KLEN  4096
#define NH    12
#define KVH   2
#define DH    128
#define HID   1536
#define KVDIM 256
#define GROUPS 6
#define NITEMS (NH * 16)

// Scratch (device globals, allocation-free), all fp16 except g_att feeds
__device__ __align__(16) __half g_q[Q_LEN * HID];      // [t][h*128+d]
__device__ __align__(16) __half g_k[KLEN * KVDIM];     // [key][kvh*128+d]
__device__ __align__(16) __half g_v[KVDIM * KLEN];     // TRANSPOSED [kvh*128+d][key]
__device__ __align__(16) __half g_att[Q_LEN * HID];    // [t][h*128+d]
__device__ __align__(16) __half g_x[Q_LEN * HID];      // [t][k]
__device__ __align__(16) __half g_wq[HID * HID];       // TRANSPOSED [n][k]
__device__ __align__(16) __half g_wk[KVDIM * HID];     // TRANSPOSED [n][k]
__device__ __align__(16) __half g_wv[KVDIM * HID];     // TRANSPOSED [n][k]
__device__ __align__(16) __half g_wo[HID * HID];       // TRANSPOSED [n][k]
__device__ unsigned int g_work;

// ---------------------------------------------------------------------------
// helpers
// ---------------------------------------------------------------------------
__device__ __forceinline__ uint32_t h2pack(float a, float b) {
    __half2 h = __floats2half2_rn(a, b);
    return *(uint32_t*)&h;
}

__device__ __forceinline__ void mma_f16(float d[4], const uint32_t a[4],
                                        const uint32_t b[2]) {
    asm volatile(
        "mma.sync.aligned.m16n8k16.row.col.f32.f16.f16.f32 "
        "{%0,%1,%2,%3}, {%4,%5,%6,%7}, {%8,%9}, {%0,%1,%2,%3};\n"
        : "+f"(d[0]), "+f"(d[1]), "+f"(d[2]), "+f"(d[3])
        : "r"(a[0]), "r"(a[1]), "r"(a[2]), "r"(a[3]), "r"(b[0]), "r"(b[1]));
}

__device__ __forceinline__ void cpa16(__half* dst, const __half* src) {
    uint32_t d = (uint32_t)__cvta_generic_to_shared(dst);
    asm volatile("cp.async.cg.shared.global [%0], [%1], 16;\n"
                 :: "r"(d), "l"(src));
}
#define CP_COMMIT() asm volatile("cp.async.commit_group;\n")
#define CP_WAIT(n)  asm volatile("cp.async.wait_group %0;\n" :: "n"(n))

// ---------------------------------------------------------------------------
// cvt: fp32 inputs -> fp16 copies (weights & v transposed); reset work queue
// ---------------------------------------------------------------------------
__global__ __launch_bounds__(256) void cvt_kernel(
    const float* __restrict__ x,  const float* __restrict__ wq,
    const float* __restrict__ wk, const float* __restrict__ wv,
    const float* __restrict__ wo, const float* __restrict__ kh,
    const float* __restrict__ vh)
{
    if (blockIdx.x == 0 && threadIdx.x == 0) g_work = 0u;
    const int SX  = Q_LEN * HID / 2;         // plain x
    const int SKH = HIST * KVDIM / 2;        // plain k_hist
    const int SWQ = HID * HID / 2;           // transpose
    const int SWK = KVDIM * HID / 2;         // transpose
    const int SWV = KVDIM * HID / 2;         // transpose
    const int SWO = HID * HID / 2;           // transpose
    const int SVH = KVDIM * HIST / 2;        // v_hist transpose
    const int total = SX + SKH + SWQ + SWK + SWV + SWO + SVH;
    int stride = gridDim.x * blockDim.x;
    for (int i = blockIdx.x * blockDim.x + threadIdx.x; i < total; i += stride) {
        int j = i;
        if (j < SX) {
            float2 v = ((const float2*)x)[j];
            ((uint32_t*)g_x)[j] = h2pack(v.x, v.y);
        } else if ((j -= SX) < SKH) {
            float2 v = ((const float2*)kh)[j];
            ((uint32_t*)g_k)[j] = h2pack(v.x, v.y);
        } else if ((j -= SKH) < SWQ) {
            int n = j / (HID / 2), kk = j % (HID / 2);
            ((uint32_t*)g_wq)[(size_t)n * (HID / 2) + kk] =
                h2pack(wq[(size_t)(2 * kk) * HID + n],
                       wq[(size_t)(2 * kk + 1) * HID + n]);
        } else if ((j -= SWQ) < SWK) {
            int n = j / (HID / 2), kk = j % (HID / 2);
            ((uint32_t*)g_wk)[(size_t)n * (HID / 2) + kk] =
                h2pack(wk[(size_t)(2 * kk) * KVDIM + n],
                       wk[(size_t)(2 * kk + 1) * KVDIM + n]);
        } else if ((j -= SWK) < SWV) {
            int n = j / (HID / 2), kk = j % (HID / 2);
            ((uint32_t*)g_wv)[(size_t)n * (HID / 2) + kk] =
                h2pack(wv[(size_t)(2 * kk) * KVDIM + n],
                       wv[(size_t)(2 * kk + 1) * KVDIM + n]);
        } else if ((j -= SWV) < SWO) {
            int n = j / (HID / 2), kk = j % (HID / 2);
            ((uint32_t*)g_wo)[(size_t)n * (HID / 2) + kk] =
                h2pack(wo[(size_t)(2 * kk) * HID + n],
                       wo[(size_t)(2 * kk + 1) * HID + n]);
        } else {
            j -= SWO;   // v_hist: [key][col] -> g_v [col][key], keys 0..HIST
            int col = j / (HIST / 2), jj = j % (HIST / 2);
            ((uint32_t*)g_v)[(size_t)col * (KLEN / 2) + jj] =
                h2pack(vh[(size_t)(2 * jj) * KVDIM + col],
                       vh[(size_t)(2 * jj + 1) * KVDIM + col]);
        }
    }
}

// ---------------------------------------------------------------------------
// fp16 GEMM, cp.async 2-stage. C[128,128] = A[M,K] @ Bt[n][k] (+bias)
// 8 warps 2x4, warp 64x32, BK=32, mma m16n8k16.
// modes: 0 = fp32 out, 1 = fp16 plain out, 2 = fp16 V-transposed out
// ---------------------------------------------------------------------------
#define LDA_G 40
#define LDB_G 40
#define GEMM_SMEM ((2 * 128 * LDA_G + 2 * 128 * LDB_G) * 2)

__device__ __forceinline__ void gemm_body_h(
    const __half* __restrict__ A, const __half* __restrict__ Bt,
    const float* __restrict__ bias, void* __restrict__ Cv,
    int row0, int col0, int K, int ldc, int mode)
{
    extern __shared__ __half smg[];
    __half* As = smg;
    __half* Bs = smg + 2 * 128 * LDA_G;

    const int tid  = threadIdx.x;
    const int w    = tid >> 5;
    const int lane = tid & 31;
    const int g    = lane >> 2;
    const int t    = lane & 3;
    const int wm   = w >> 2;
    const int wn   = w & 3;

    float acc[16][4];
#pragma unroll
    for (int i = 0; i < 16; i++)
#pragma unroll
        for (int j = 0; j < 4; j++) acc[i][j] = 0.f;

    auto load_stage = [&](int s, int k0) {
#pragma unroll
        for (int l = 0; l < 2; l++) {
            int i = tid + l * 256;
            int r = i >> 2, c = (i & 3) << 3;
            cpa16(As + (s * 128 + r) * LDA_G + c,
                  A + (size_t)(row0 + r) * K + k0 + c);
        }
#pragma unroll
        for (int l = 0; l < 2; l++) {
            int i = tid + l * 256;
            int r = i >> 2, c = (i & 3) << 3;
            cpa16(Bs + (s * 128 + r) * LDB_G + c,
                  Bt + (size_t)(col0 + r) * K + k0 + c);
        }
        CP_COMMIT();
    };

    load_stage(0, 0);
    const int KT = K / 32;
    for (int kt = 0; kt < KT; kt++) {
        if (kt + 1 < KT) { load_stage((kt + 1) & 1, (kt + 1) * 32); CP_WAIT(1); }
        else             { CP_WAIT(0); }
        __syncthreads();
        const __half* Ab = As + (kt & 1) * 128 * LDA_G;
        const __half* Bb = Bs + (kt & 1) * 128 * LDB_G;
#pragma unroll
        for (int k16 = 0; k16 < 32; k16 += 16) {
            uint32_t a[4][4];
#pragma unroll
            for (int mi = 0; mi < 4; mi++) {
                const __half* ab = Ab + (wm * 64 + mi * 16 + g) * LDA_G + k16;
                a[mi][0] = *(const uint32_t*)(ab + 2 * t);
                a[mi][1] = *(const uint32_t*)(ab + 8 * LDA_G + 2 * t);
                a[mi][2] = *(const uint32_t*)(ab + 2 * t + 8);
                a[mi][3] = *(const uint32_t*)(ab + 8 * LDA_G + 2 * t + 8);
            }
#pragma unroll
            for (int ni = 0; ni < 4; ni++) {
                const __half* bp = Bb + (wn * 32 + ni * 8 + g) * LDB_G + k16;
                uint32_t b[2];
                b[0] = *(const uint32_t*)(bp + 2 * t);
                b[1] = *(const uint32_t*)(bp + 2 * t + 8);
#pragma unroll
                for (int mi = 0; mi < 4; mi++)
                    mma_f16(acc[mi * 4 + ni], a[mi], b);
            }
        }
        __syncthreads();
    }

#pragma unroll
    for (int mi = 0; mi < 4; mi++)
#pragma unroll
        for (int ni = 0; ni < 4; ni++) {
            int col = col0 + wn * 32 + ni * 8 + 2 * t;
            float b0 = bias ? bias[col]     : 0.f;
            float b1 = bias ? bias[col + 1] : 0.f;
            int r0 = row0 + wm * 64 + mi * 16 + g;
            float v00 = acc[mi * 4 + ni][0] + b0;
            float v01 = acc[mi * 4 + ni][1] + b1;
            float v10 = acc[mi * 4 + ni][2] + b0;
            float v11 = acc[mi * 4 + ni][3] + b1;
            if (mode == 0) {
                float* C = (float*)Cv;
                *(float2*)(C + (size_t)r0 * ldc + col)       = make_float2(v00, v01);
                *(float2*)(C + (size_t)(r0 + 8) * ldc + col) = make_float2(v10, v11);
            } else if (mode == 1) {
                __half* C = (__half*)Cv;
                *(uint32_t*)(C + (size_t)r0 * ldc + col)       = h2pack(v00, v01);
                *(uint32_t*)(C + (size_t)(r0 + 8) * ldc + col) = h2pack(v10, v11);
            } else {
                // V transposed: g_v[col][key], key = HIST + r0
                __half* C = (__half*)Cv;
                int key = HIST + r0;
                C[(size_t)col * KLEN + key]           = __float2half_rn(v00);
                C[(size_t)(col + 1) * KLEN + key]     = __float2half_rn(v01);
                C[(size_t)col * KLEN + key + 8]       = __float2half_rn(v10);
                C[(size_t)(col + 1) * KLEN + key + 8] = __float2half_rn(v11);
            }
        }
}

// grid.x: 0..11 -> Wq, 12..13 -> Wk, 14..15 -> Wv
__global__ __launch_bounds__(256) void gemm_qkv_kernel(
    const float* __restrict__ bq, const float* __restrict__ bk,
    const float* __restrict__ bv)
{
    int bx   = blockIdx.x;
    int row0 = blockIdx.y * 128;
    if (bx < 12) {
        gemm_body_h(g_x, g_wq, bq, g_q, row0, bx * 128, HID, HID, 1);
    } else if (bx < 14) {
        gemm_body_h(g_x, g_wk, bk, g_k + (size_t)HIST * KVDIM, row0,
                    (bx - 12) * 128, HID, KVDIM, 1);
    } else {
        gemm_body_h(g_x, g_wv, bv, g_v, row0, (bx - 14) * 128, HID, 0, 2);
    }
}

__global__ __launch_bounds__(256) void gemm_wo_kernel(float* __restrict__ out)
{
    gemm_body_h(g_att, g_wo, nullptr, out, blockIdx.y * 128,
                blockIdx.x * 128, HID, HID, 0);
}

// ---------------------------------------------------------------------------
// RoPE in fp16 (compute fp32): Q heads and new K rows
// ---------------------------------------------------------------------------
__global__ __launch_bounds__(64) void rope_kernel(
    const float* __restrict__ fcos, const float* __restrict__ fsin)
{
    int b  = blockIdx.x;
    int t  = b / 14;
    int hh = b % 14;
    int d  = threadIdx.x;   // 0..63
    float c = fcos[t * 64 + d];
    float s = fsin[t * 64 + d];
    __half* base;
    if (hh < 12) base = g_q + (size_t)t * HID + hh * DH;
    else         base = g_k + (size_t)(HIST + t) * KVDIM + (hh - 12) * DH;
    float x1 = __half2float(base[d]);
    float x2 = __half2float(base[d + 64]);
    base[d]      = __float2half_rn(x1 * c - x2 * s);
    base[d + 64] = __float2half_rn(x1 * s + x2 * c);
}

// ---------------------------------------------------------------------------
// Persistent flash attention, fp16 mma m16n8k16.
// Q frags in regs; K double-buffered; V (transposed) overlapped behind S.
// ---------------------------------------------------------------------------
#define LDQ 136   // halves
#define LDK 136
#define LDVT 72
#define LDP 72
#define AQ_H (128 * LDQ)
#define AK_H (2 * 64 * LDK)
#define AV_H (128 * LDVT)
#define AP_H (128 * LDP)
#define AW_H (AQ_H + AK_H + AV_H + AP_H)
#define ATTN_SMEM (AW_H * 2 + 16)

__global__ __launch_bounds__(256) void attn_kernel()
{
    extern __shared__ __half smh[];
    __half* Qs = smh;
    __half* Ks = smh + AQ_H;
    __half* Vs = smh + AQ_H + AK_H;
    __half* Ps = smh + AQ_H + AK_H + AV_H;
    int* widx = (int*)(smh + AW_H);

    const int tid  = threadIdx.x;
    const int w    = tid >> 5;
    const int lane = tid & 31;
    const int g    = lane >> 2;
    const int t    = lane & 3;
    const float SC = 0.12751689932560563f;  // 1/sqrt(128) * log2(e)

    for (;;) {
        if (tid == 0) *widx = (int)atomicAdd(&g_work, 1u);
        __syncthreads();
        const int item = *widx;
        if (item >= NITEMS) break;
        const int qt   = 15 - item / NH;     // descending nkt (LPT)
        const int head = item % NH;
        const int q0   = qt * 128;
        const int kvh  = head / GROUPS;

        // Q tile -> smem (128 rows x 128 halves)
#pragma unroll
        for (int l = 0; l < 8; l++) {
            int i = tid + l * 256;
            int r = i >> 4, c = (i & 15) << 3;
            cpa16(Qs + r * LDQ + c, g_q + (size_t)(q0 + r) * HID + head * DH + c);
        }
        CP_COMMIT();
        // K(0) into stage 0 (64 rows x 128 halves)
#pragma unroll
        for (int l = 0; l < 4; l++) {
            int i = tid + l * 256;
            int r = i >> 4, c = (i & 15) << 3;
            cpa16(Ks + r * LDK + c, g_k + (size_t)r * KVDIM + kvh * DH + c);
        }
        CP_COMMIT();

        // retire Q, capture Q fragments (8 k16-steps x 4 regs)
        CP_WAIT(1);
        __syncthreads();
        uint32_t qf[8][4];
#pragma unroll
        for (int k16 = 0; k16 < 8; k16++) {
            const __half* qb = Qs + (w * 16 + g) * LDQ + k16 * 16;
            qf[k16][0] = *(const uint32_t*)(qb + 2 * t);
            qf[k16][1] = *(const uint32_t*)(qb + 8 * LDQ + 2 * t);
            qf[k16][2] = *(const uint32_t*)(qb + 2 * t + 8);
            qf[k16][3] = *(const uint32_t*)(qb + 8 * LDQ + 2 * t + 8);
        }

        float o[16][4];
#pragma unroll
        for (int i = 0; i < 16; i++)
#pragma unroll
            for (int j = 0; j < 4; j++) o[i][j] = 0.f;
        float m0 = -1e30f, m1 = -1e30f, l0 = 0.f, l1 = 0.f;
        const int row0g = q0 + w * 16 + g;
        const int nkt = (q0 + 128 + HIST) / 64;

        for (int kt = 0; kt < nkt; kt++) {
            const int kb = kt * 64;
            const __half* Kcur = Ks + (kt & 1) * 64 * LDK;
            const bool more = (kt + 1 < nkt);

            // issue V(kt): transposed tile 128 d-rows x 64 halves
#pragma unroll
            for (int l = 0; l < 4; l++) {
                int i = tid + l * 256;
                int r = i >> 3, c = (i & 7) << 3;
                cpa16(Vs + r * LDVT + c,
                      g_v + (size_t)(kvh * DH + r) * KLEN + kb + c);
            }
            CP_COMMIT();
            // issue K(kt+1)
            if (more) {
                __half* Knx = Ks + ((kt + 1) & 1) * 64 * LDK;
#pragma unroll
                for (int l = 0; l < 4; l++) {
                    int i = tid + l * 256;
                    int r = i >> 4, c = (i & 15) << 3;
                    cpa16(Knx + r * LDK + c,
                          g_k + (size_t)(kb + 64 + r) * KVDIM + kvh * DH + c);
                }
                CP_COMMIT();
                CP_WAIT(2);          // K(kt) ready
            } else {
                CP_WAIT(1);
            }
            __syncthreads();

            // S = Q K^T
            float s[8][4];
#pragma unroll
            for (int j = 0; j < 8; j++)
#pragma unroll
                for (int e = 0; e < 4; e++) s[j][e] = 0.f;
#pragma unroll
            for (int k16 = 0; k16 < 8; k16++) {
#pragma unroll
                for (int j = 0; j < 8; j++) {
                    const __half* kp = Kcur + (j * 8 + g) * LDK + k16 * 16;
                    uint32_t b[2];
                    b[0] = *(const uint32_t*)(kp + 2 * t);
                    b[1] = *(const uint32_t*)(kp + 2 * t + 8);
                    mma_f16(s[j], qf[k16], b);
                }
            }

            // scale + (rare) causal mask
            if (kb + 63 > q0 + HIST) {
#pragma unroll
                for (int j = 0; j < 8; j++) {
                    int colg = kb + j * 8 + 2 * t;
                    s[j][0] = (colg     <= row0g + HIST)     ? s[j][0] * SC : -1e30f;
                    s[j][1] = (colg + 1 <= row0g + HIST)     ? s[j][1] * SC : -1e30f;
                    s[j][2] = (colg     <= row0g + 8 + HIST) ? s[j][2] * SC : -1e30f;
                    s[j][3] = (colg + 1 <= row0g + 8 + HIST) ? s[j][3] * SC : -1e30f;
                }
            } else {
#pragma unroll
                for (int j = 0; j < 8; j++) {
                    s[j][0] *= SC; s[j][1] *= SC;
                    s[j][2] *= SC; s[j][3] *= SC;
                }
            }

            // online softmax (quad reduce)
            float mx0 = -1e30f, mx1 = -1e30f;
#pragma unroll
            for (int j = 0; j < 8; j++) {
                mx0 = fmaxf(mx0, fmaxf(s[j][0], s[j][1]));
                mx1 = fmaxf(mx1, fmaxf(s[j][2], s[j][3]));
            }
            mx0 = fmaxf(mx0, __shfl_xor_sync(0xffffffffu, mx0, 1));
            mx0 = fmaxf(mx0, __shfl_xor_sync(0xffffffffu, mx0, 2));
            mx1 = fmaxf(mx1, __shfl_xor_sync(0xffffffffu, mx1, 1));
            mx1 = fmaxf(mx1, __shfl_xor_sync(0xffffffffu, mx1, 2));
            float mn0 = fmaxf(m0, mx0), mn1 = fmaxf(m1, mx1);
            float c0 = exp2f(m0 - mn0), c1 = exp2f(m1 - mn1);
            m0 = mn0; m1 = mn1;
            float sum0 = 0.f, sum1 = 0.f;
#pragma unroll
            for (int j = 0; j < 8; j++) {
                s[j][0] = exp2f(s[j][0] - m0);
                s[j][1] = exp2f(s[j][1] - m0);
                s[j][2] = exp2f(s[j][2] - m1);
                s[j][3] = exp2f(s[j][3] - m1);
                sum0 += s[j][0] + s[j][1];
                sum1 += s[j][2] + s[j][3];
            }
            sum0 += __shfl_xor_sync(0xffffffffu, sum0, 1);
            sum0 += __shfl_xor_sync(0xffffffffu, sum0, 2);
            sum1 += __shfl_xor_sync(0xffffffffu, sum1, 1);
            sum1 += __shfl_xor_sync(0xffffffffu, sum1, 2);
            l0 = l0 * c0 + sum0;
            l1 = l1 * c1 + sum1;

#pragma unroll
            for (int j = 0; j < 16; j++) {
                o[j][0] *= c0; o[j][1] *= c0;
                o[j][2] *= c1; o[j][3] *= c1;
            }

            // stage P as half2 (natural accumulator layout)
            {
                __half* p0 = Ps + (w * 16 + g) * LDP;
                __half* p1 = p0 + 8 * LDP;
#pragma unroll
                for (int j = 0; j < 8; j++) {
                    *(uint32_t*)(p0 + j * 8 + 2 * t) = h2pack(s[j][0], s[j][1]);
                    *(uint32_t*)(p1 + j * 8 + 2 * t) = h2pack(s[j][2], s[j][3]);
                }
            }
            __syncwarp();

            if (more) { CP_WAIT(1); } else { CP_WAIT(0); }   // V(kt) ready
            __syncthreads();

            // O += P @ V   (V transposed: b-frags along key dim)
#pragma unroll
            for (int k16 = 0; k16 < 4; k16++) {
                const __half* pb = Ps + (w * 16 + g) * LDP + k16 * 16;
                uint32_t a[4];
                a[0] = *(const uint32_t*)(pb + 2 * t);
                a[1] = *(const uint32_t*)(pb + 8 * LDP + 2 * t);
                a[2] = *(const uint32_t*)(pb + 2 * t + 8);
                a[3] = *(const uint32_t*)(pb + 8 * LDP + 2 * t + 8);
#pragma unroll
                for (int j = 0; j < 16; j++) {
                    const __half* vb = Vs + (j * 8 + g) * LDVT + k16 * 16;
                    uint32_t b[2];
                    b[0] = *(const uint32_t*)(vb + 2 * t);
                    b[1] = *(const uint32_t*)(vb + 2 * t + 8);
                    mma_f16(o[j], a, b);
                }
            }
            __syncthreads();
        }

        // normalize + store fp16 (feeds Wo GEMM)
        float inv0 = 1.f / l0, inv1 = 1.f / l1;
#pragma unroll
        for (int j = 0; j < 16; j++) {
            __half* a0 = g_att + (size_t)row0g * HID + head * DH + j * 8 + 2 * t;
            __half* a1 = a0 + 8 * HID;
            *(uint32_t*)a0 = h2pack(o[j][0] * inv0, o[j][1] * inv0);
            *(uint32_t*)a1 = h2pack(o[j][2] * inv1, o[j][3] * inv1);
        }
        __syncthreads();
    }
}

// ---------------------------------------------------------------------------
extern "C" void kernel_launch(void* const* d_in, const int* in_sizes, int n_in,
                              void* d_out, int out_size)
{
    const float* x      = (const float*)d_in[0];
    const float* Wq     = (const float*)d_in[1];
    const float* bq     = (const float*)d_in[2];
    const float* Wk     = (const float*)d_in[3];
    const float* bk     = (const float*)d_in[4];
    const float* Wv     = (const float*)d_in[5];
    const float* bv     = (const float*)d_in[6];
    const float* Wo     = (const float*)d_in[7];
    const float* k_hist = (const float*)d_in[8];
    const float* v_hist = (const float*)d_in[9];
    const float* fcos   = (const float*)d_in[10];
    const float* fsin   = (const float*)d_in[11];
    float* out = (float*)d_out;

    cudaFuncSetAttribute(attn_kernel,
                         cudaFuncAttributeMaxDynamicSharedMemorySize, ATTN_SMEM);
    cudaFuncSetAttribute(gemm_qkv_kernel,
                         cudaFuncAttributeMaxDynamicSharedMemorySize, GEMM_SMEM);
    cudaFuncSetAttribute(gemm_wo_kernel,
                         cudaFuncAttributeMaxDynamicSharedMemorySize, GEMM_SMEM);

    // fp32 -> fp16 copies (weights/v transposed); reset work queue
    cvt_kernel<<<2368, 256>>>(x, Wq, Wk, Wv, Wo, k_hist, v_hist);

    // fused QKV projection (fp16 mma)
    gemm_qkv_kernel<<<dim3(16, 16), 256, GEMM_SMEM>>>(bq, bk, bv);

    // RoPE
    rope_kernel<<<Q_LEN * 14, 64>>>(fcos, fsin);

    // attention (persistent, LPT work queue, fp16 mma)
    attn_kernel<<<148, 256, ATTN_SMEM>>>();

    // output projection (fp32 out)
    gemm_wo_kernel<<<dim3(HID / 128, Q_LEN / 128), 256, GEMM_SMEM>>>(out);
}

// round 10
// speedup vs baseline: 2.7687x; 1.1035x over previous
#include <cuda_runtime.h>
#include <cuda_fp16.h>
#include <math_constants.h>
#include <cstdint>

#define Q_LEN 2048
#define HIST  2048
#define KLEN  4096
#define NH    12
#define KVH   2
#define DH    128
#define HID   1536
#define KVDIM 256
#define GROUPS 6
#define NITEMS (NH * 16)

// Scratch (device globals, allocation-free)
__device__ __align__(16) __half g_q[Q_LEN * HID];      // [t][h*128+d]
__device__ __align__(16) __half g_k[KLEN * KVDIM];     // [key][kvh*128+d]
__device__ __align__(16) __half g_v[KVDIM * KLEN];     // TRANSPOSED [kvh*128+d][key]
__device__ __align__(16) __half g_att[Q_LEN * HID];    // [t][h*128+d]
__device__ __align__(16) __half g_x[Q_LEN * HID];      // [t][k]
__device__ __align__(16) __half g_wq[HID * HID];       // TRANSPOSED [n][k]
__device__ __align__(16) __half g_wk[KVDIM * HID];     // TRANSPOSED [n][k]
__device__ __align__(16) __half g_wv[KVDIM * HID];     // TRANSPOSED [n][k]
__device__ __align__(16) __half g_wo[HID * HID];       // TRANSPOSED [n][k]
__device__ unsigned int g_work;

// ---------------------------------------------------------------------------
// helpers
// ---------------------------------------------------------------------------
__device__ __forceinline__ uint32_t h2pack(float a, float b) {
    __half2 h = __floats2half2_rn(a, b);
    return *(uint32_t*)&h;
}

__device__ __forceinline__ void mma_f16(float d[4], const uint32_t a[4],
                                        const uint32_t b[2]) {
    asm volatile(
        "mma.sync.aligned.m16n8k16.row.col.f32.f16.f16.f32 "
        "{%0,%1,%2,%3}, {%4,%5,%6,%7}, {%8,%9}, {%0,%1,%2,%3};\n"
        : "+f"(d[0]), "+f"(d[1]), "+f"(d[2]), "+f"(d[3])
        : "r"(a[0]), "r"(a[1]), "r"(a[2]), "r"(a[3]), "r"(b[0]), "r"(b[1]));
}

__device__ __forceinline__ void cpa16(__half* dst, const __half* src) {
    uint32_t d = (uint32_t)__cvta_generic_to_shared(dst);
    asm volatile("cp.async.cg.shared.global [%0], [%1], 16;\n"
                 :: "r"(d), "l"(src));
}
#define CP_COMMIT() asm volatile("cp.async.commit_group;\n")
#define CP_WAIT(n)  asm volatile("cp.async.wait_group %0;\n" :: "n"(n))

// ---------------------------------------------------------------------------
// cvt: fp32 inputs -> fp16 copies (weights & v transposed); reset work queue
// ---------------------------------------------------------------------------
__global__ __launch_bounds__(256) void cvt_kernel(
    const float* __restrict__ x,  const float* __restrict__ wq,
    const float* __restrict__ wk, const float* __restrict__ wv,
    const float* __restrict__ wo, const float* __restrict__ kh,
    const float* __restrict__ vh)
{
    if (blockIdx.x == 0 && threadIdx.x == 0) g_work = 0u;
    const int SX  = Q_LEN * HID / 2;
    const int SKH = HIST * KVDIM / 2;
    const int SWQ = HID * HID / 2;
    const int SWK = KVDIM * HID / 2;
    const int SWV = KVDIM * HID / 2;
    const int SWO = HID * HID / 2;
    const int SVH = KVDIM * HIST / 2;
    const int total = SX + SKH + SWQ + SWK + SWV + SWO + SVH;
    int stride = gridDim.x * blockDim.x;
    for (int i = blockIdx.x * blockDim.x + threadIdx.x; i < total; i += stride) {
        int j = i;
        if (j < SX) {
            float2 v = ((const float2*)x)[j];
            ((uint32_t*)g_x)[j] = h2pack(v.x, v.y);
        } else if ((j -= SX) < SKH) {
            float2 v = ((const float2*)kh)[j];
            ((uint32_t*)g_k)[j] = h2pack(v.x, v.y);
        } else if ((j -= SKH) < SWQ) {
            int n = j / (HID / 2), kk = j % (HID / 2);
            ((uint32_t*)g_wq)[(size_t)n * (HID / 2) + kk] =
                h2pack(wq[(size_t)(2 * kk) * HID + n],
                       wq[(size_t)(2 * kk + 1) * HID + n]);
        } else if ((j -= SWQ) < SWK) {
            int n = j / (HID / 2), kk = j % (HID / 2);
            ((uint32_t*)g_wk)[(size_t)n * (HID / 2) + kk] =
                h2pack(wk[(size_t)(2 * kk) * KVDIM + n],
                       wk[(size_t)(2 * kk + 1) * KVDIM + n]);
        } else if ((j -= SWK) < SWV) {
            int n = j / (HID / 2), kk = j % (HID / 2);
            ((uint32_t*)g_wv)[(size_t)n * (HID / 2) + kk] =
                h2pack(wv[(size_t)(2 * kk) * KVDIM + n],
                       wv[(size_t)(2 * kk + 1) * KVDIM + n]);
        } else if ((j -= SWV) < SWO) {
            int n = j / (HID / 2), kk = j % (HID / 2);
            ((uint32_t*)g_wo)[(size_t)n * (HID / 2) + kk] =
                h2pack(wo[(size_t)(2 * kk) * HID + n],
                       wo[(size_t)(2 * kk + 1) * HID + n]);
        } else {
            j -= SWO;   // v_hist: [key][col] -> g_v [col][key]
            int col = j / (HIST / 2), jj = j % (HIST / 2);
            ((uint32_t*)g_v)[(size_t)col * (KLEN / 2) + jj] =
                h2pack(vh[(size_t)(2 * jj) * KVDIM + col],
                       vh[(size_t)(2 * jj + 1) * KVDIM + col]);
        }
    }
}

// ---------------------------------------------------------------------------
// fp16 GEMM, cp.async 2-stage. C[128,128] = A[M,K] @ Bt[n][k] (+bias)
// modes: 0 = fp32 out, 1 = fp16 plain out, 2 = fp16 V-transposed out
// ---------------------------------------------------------------------------
#define LDA_G 40
#define LDB_G 40
#define GEMM_SMEM ((2 * 128 * LDA_G + 2 * 128 * LDB_G) * 2)

__device__ __forceinline__ void gemm_body_h(
    const __half* __restrict__ A, const __half* __restrict__ Bt,
    const float* __restrict__ bias, void* __restrict__ Cv,
    int row0, int col0, int K, int ldc, int mode)
{
    extern __shared__ __half smg[];
    __half* As = smg;
    __half* Bs = smg + 2 * 128 * LDA_G;

    const int tid  = threadIdx.x;
    const int w    = tid >> 5;
    const int lane = tid & 31;
    const int g    = lane >> 2;
    const int t    = lane & 3;
    const int wm   = w >> 2;
    const int wn   = w & 3;

    float acc[16][4];
#pragma unroll
    for (int i = 0; i < 16; i++)
#pragma unroll
        for (int j = 0; j < 4; j++) acc[i][j] = 0.f;

    auto load_stage = [&](int s, int k0) {
#pragma unroll
        for (int l = 0; l < 2; l++) {
            int i = tid + l * 256;
            int r = i >> 2, c = (i & 3) << 3;
            cpa16(As + (s * 128 + r) * LDA_G + c,
                  A + (size_t)(row0 + r) * K + k0 + c);
        }
#pragma unroll
        for (int l = 0; l < 2; l++) {
            int i = tid + l * 256;
            int r = i >> 2, c = (i & 3) << 3;
            cpa16(Bs + (s * 128 + r) * LDB_G + c,
                  Bt + (size_t)(col0 + r) * K + k0 + c);
        }
        CP_COMMIT();
    };

    load_stage(0, 0);
    const int KT = K / 32;
    for (int kt = 0; kt < KT; kt++) {
        if (kt + 1 < KT) { load_stage((kt + 1) & 1, (kt + 1) * 32); CP_WAIT(1); }
        else             { CP_WAIT(0); }
        __syncthreads();
        const __half* Ab = As + (kt & 1) * 128 * LDA_G;
        const __half* Bb = Bs + (kt & 1) * 128 * LDB_G;
#pragma unroll
        for (int k16 = 0; k16 < 32; k16 += 16) {
            uint32_t a[4][4];
#pragma unroll
            for (int mi = 0; mi < 4; mi++) {
                const __half* ab = Ab + (wm * 64 + mi * 16 + g) * LDA_G + k16;
                a[mi][0] = *(const uint32_t*)(ab + 2 * t);
                a[mi][1] = *(const uint32_t*)(ab + 8 * LDA_G + 2 * t);
                a[mi][2] = *(const uint32_t*)(ab + 2 * t + 8);
                a[mi][3] = *(const uint32_t*)(ab + 8 * LDA_G + 2 * t + 8);
            }
#pragma unroll
            for (int ni = 0; ni < 4; ni++) {
                const __half* bp = Bb + (wn * 32 + ni * 8 + g) * LDB_G + k16;
                uint32_t b[2];
                b[0] = *(const uint32_t*)(bp + 2 * t);
                b[1] = *(const uint32_t*)(bp + 2 * t + 8);
#pragma unroll
                for (int mi = 0; mi < 4; mi++)
                    mma_f16(acc[mi * 4 + ni], a[mi], b);
            }
        }
        __syncthreads();
    }

#pragma unroll
    for (int mi = 0; mi < 4; mi++)
#pragma unroll
        for (int ni = 0; ni < 4; ni++) {
            int col = col0 + wn * 32 + ni * 8 + 2 * t;
            float b0 = bias ? bias[col]     : 0.f;
            float b1 = bias ? bias[col + 1] : 0.f;
            int r0 = row0 + wm * 64 + mi * 16 + g;
            float v00 = acc[mi * 4 + ni][0] + b0;
            float v01 = acc[mi * 4 + ni][1] + b1;
            float v10 = acc[mi * 4 + ni][2] + b0;
            float v11 = acc[mi * 4 + ni][3] + b1;
            if (mode == 0) {
                float* C = (float*)Cv;
                *(float2*)(C + (size_t)r0 * ldc + col)       = make_float2(v00, v01);
                *(float2*)(C + (size_t)(r0 + 8) * ldc + col) = make_float2(v10, v11);
            } else if (mode == 1) {
                __half* C = (__half*)Cv;
                *(uint32_t*)(C + (size_t)r0 * ldc + col)       = h2pack(v00, v01);
                *(uint32_t*)(C + (size_t)(r0 + 8) * ldc + col) = h2pack(v10, v11);
            } else {
                __half* C = (__half*)Cv;
                int key = HIST + r0;
                C[(size_t)col * KLEN + key]           = __float2half_rn(v00);
                C[(size_t)(col + 1) * KLEN + key]     = __float2half_rn(v01);
                C[(size_t)col * KLEN + key + 8]       = __float2half_rn(v10);
                C[(size_t)(col + 1) * KLEN + key + 8] = __float2half_rn(v11);
            }
        }
}

// grid.x: 0..11 -> Wq, 12..13 -> Wk, 14..15 -> Wv
__global__ __launch_bounds__(256) void gemm_qkv_kernel(
    const float* __restrict__ bq, const float* __restrict__ bk,
    const float* __restrict__ bv)
{
    int bx   = blockIdx.x;
    int row0 = blockIdx.y * 128;
    if (bx < 12) {
        gemm_body_h(g_x, g_wq, bq, g_q, row0, bx * 128, HID, HID, 1);
    } else if (bx < 14) {
        gemm_body_h(g_x, g_wk, bk, g_k + (size_t)HIST * KVDIM, row0,
                    (bx - 12) * 128, HID, KVDIM, 1);
    } else {
        gemm_body_h(g_x, g_wv, bv, g_v, row0, (bx - 14) * 128, HID, 0, 2);
    }
}

__global__ __launch_bounds__(256) void gemm_wo_kernel(float* __restrict__ out)
{
    gemm_body_h(g_att, g_wo, nullptr, out, blockIdx.y * 128,
                blockIdx.x * 128, HID, HID, 0);
}

// ---------------------------------------------------------------------------
// RoPE in fp16 (compute fp32)
// ---------------------------------------------------------------------------
__global__ __launch_bounds__(64) void rope_kernel(
    const float* __restrict__ fcos, const float* __restrict__ fsin)
{
    int b  = blockIdx.x;
    int t  = b / 14;
    int hh = b % 14;
    int d  = threadIdx.x;
    float c = fcos[t * 64 + d];
    float s = fsin[t * 64 + d];
    __half* base;
    if (hh < 12) base = g_q + (size_t)t * HID + hh * DH;
    else         base = g_k + (size_t)(HIST + t) * KVDIM + (hh - 12) * DH;
    float x1 = __half2float(base[d]);
    float x2 = __half2float(base[d + 64]);
    base[d]      = __float2half_rn(x1 * c - x2 * s);
    base[d + 64] = __float2half_rn(x1 * s + x2 * c);
}

// ---------------------------------------------------------------------------
// Persistent flash attention, fp16 mma, KTILE=128 keys, ONE barrier per tile.
// K and V (transposed) both double-buffered; next-tile loads issued right
// after the top-of-tile barrier (barrier proves prior tile fully consumed).
// ---------------------------------------------------------------------------
#define KTILE 128
#define LDQ 136   // halves
#define LDK 136
#define LDVT 136
#define LDP 136
#define AQ_H (128 * LDQ)
#define AK_H (2 * 128 * LDK)
#define AV_H (2 * 128 * LDVT)
#define AP_H (128 * LDP)
#define AW_H (AQ_H + AK_H + AV_H + AP_H)
#define ATTN_SMEM (AW_H * 2 + 16)

__global__ __launch_bounds__(256) void attn_kernel()
{
    extern __shared__ __half smh[];
    __half* Qs = smh;
    __half* Ks = smh + AQ_H;
    __half* Vs = smh + AQ_H + AK_H;
    __half* Ps = smh + AQ_H + AK_H + AV_H;
    int* widx = (int*)(smh + AW_H);

    const int tid  = threadIdx.x;
    const int w    = tid >> 5;
    const int lane = tid & 31;
    const int g    = lane >> 2;
    const int t    = lane & 3;
    const float SC = 0.12751689932560563f;  // 1/sqrt(128) * log2(e)

    for (;;) {
        if (tid == 0) *widx = (int)atomicAdd(&g_work, 1u);
        __syncthreads();
        const int item = *widx;
        if (item >= NITEMS) break;
        const int qt   = 15 - item / NH;     // descending nkt (LPT)
        const int head = item % NH;
        const int q0   = qt * 128;
        const int kvh  = head / GROUPS;

        // Q tile (128 x 128 halves)
#pragma unroll
        for (int l = 0; l < 8; l++) {
            int i = tid + l * 256;
            int r = i >> 4, c = (i & 15) << 3;
            cpa16(Qs + r * LDQ + c, g_q + (size_t)(q0 + r) * HID + head * DH + c);
        }
        // K(0), V(0) into stage 0 (one group with Q)
#pragma unroll
        for (int l = 0; l < 8; l++) {
            int i = tid + l * 256;
            int r = i >> 4, c = (i & 15) << 3;
            cpa16(Ks + r * LDK + c, g_k + (size_t)r * KVDIM + kvh * DH + c);
        }
#pragma unroll
        for (int l = 0; l < 8; l++) {
            int i = tid + l * 256;
            int r = i >> 4, c = (i & 15) << 3;
            cpa16(Vs + r * LDVT + c, g_v + (size_t)(kvh * DH + r) * KLEN + c);
        }
        CP_COMMIT();
        CP_WAIT(0);
        __syncthreads();

        // capture Q fragments
        uint32_t qf[8][4];
#pragma unroll
        for (int k16 = 0; k16 < 8; k16++) {
            const __half* qb = Qs + (w * 16 + g) * LDQ + k16 * 16;
            qf[k16][0] = *(const uint32_t*)(qb + 2 * t);
            qf[k16][1] = *(const uint32_t*)(qb + 8 * LDQ + 2 * t);
            qf[k16][2] = *(const uint32_t*)(qb + 2 * t + 8);
            qf[k16][3] = *(const uint32_t*)(qb + 8 * LDQ + 2 * t + 8);
        }

        float o[16][4];
#pragma unroll
        for (int i = 0; i < 16; i++)
#pragma unroll
            for (int j = 0; j < 4; j++) o[i][j] = 0.f;
        float m0 = -1e30f, m1 = -1e30f, l0 = 0.f, l1 = 0.f;
        const int row0g = q0 + w * 16 + g;
        const int nkt = qt + 17;             // (q0 + 128 + HIST) / KTILE

        for (int kt = 0; kt < nkt; kt++) {
            const int kb = kt * KTILE;
            if (kt > 0) {
                CP_WAIT(0);          // K(kt), V(kt) arrived
                __syncthreads();     // ...and tile kt-1 fully consumed
            }
            // issue K(kt+1), V(kt+1) into the other buffers
            if (kt + 1 < nkt) {
                __half* Knx = Ks + ((kt + 1) & 1) * 128 * LDK;
                __half* Vnx = Vs + ((kt + 1) & 1) * 128 * LDVT;
#pragma unroll
                for (int l = 0; l < 8; l++) {
                    int i = tid + l * 256;
                    int r = i >> 4, c = (i & 15) << 3;
                    cpa16(Knx + r * LDK + c,
                          g_k + (size_t)(kb + KTILE + r) * KVDIM + kvh * DH + c);
                }
#pragma unroll
                for (int l = 0; l < 8; l++) {
                    int i = tid + l * 256;
                    int r = i >> 4, c = (i & 15) << 3;
                    cpa16(Vnx + r * LDVT + c,
                          g_v + (size_t)(kvh * DH + r) * KLEN + kb + KTILE + c);
                }
                CP_COMMIT();
            }

            const __half* Kcur = Ks + (kt & 1) * 128 * LDK;
            const __half* Vcur = Vs + (kt & 1) * 128 * LDVT;

            // S = Q K^T : 16 rows x 128 keys per warp
            float s[16][4];
#pragma unroll
            for (int j = 0; j < 16; j++)
#pragma unroll
                for (int e = 0; e < 4; e++) s[j][e] = 0.f;
#pragma unroll
            for (int k16 = 0; k16 < 8; k16++) {
#pragma unroll
                for (int j = 0; j < 16; j++) {
                    const __half* kp = Kcur + (j * 8 + g) * LDK + k16 * 16;
                    uint32_t b[2];
                    b[0] = *(const uint32_t*)(kp + 2 * t);
                    b[1] = *(const uint32_t*)(kp + 2 * t + 8);
                    mma_f16(s[j], qf[k16], b);
                }
            }

            // scale + causal mask (only the final tile is partial)
            if (kt == nkt - 1) {
#pragma unroll
                for (int j = 0; j < 16; j++) {
                    int colg = kb + j * 8 + 2 * t;
                    s[j][0] = (colg     <= row0g + HIST)     ? s[j][0] * SC : -1e30f;
                    s[j][1] = (colg + 1 <= row0g + HIST)     ? s[j][1] * SC : -1e30f;
                    s[j][2] = (colg     <= row0g + 8 + HIST) ? s[j][2] * SC : -1e30f;
                    s[j][3] = (colg + 1 <= row0g + 8 + HIST) ? s[j][3] * SC : -1e30f;
                }
            } else {
#pragma unroll
                for (int j = 0; j < 16; j++) {
                    s[j][0] *= SC; s[j][1] *= SC;
                    s[j][2] *= SC; s[j][3] *= SC;
                }
            }

            // online softmax (quad reduce)
            float mx0 = -1e30f, mx1 = -1e30f;
#pragma unroll
            for (int j = 0; j < 16; j++) {
                mx0 = fmaxf(mx0, fmaxf(s[j][0], s[j][1]));
                mx1 = fmaxf(mx1, fmaxf(s[j][2], s[j][3]));
            }
            mx0 = fmaxf(mx0, __shfl_xor_sync(0xffffffffu, mx0, 1));
            mx0 = fmaxf(mx0, __shfl_xor_sync(0xffffffffu, mx0, 2));
            mx1 = fmaxf(mx1, __shfl_xor_sync(0xffffffffu, mx1, 1));
            mx1 = fmaxf(mx1, __shfl_xor_sync(0xffffffffu, mx1, 2));
            float mn0 = fmaxf(m0, mx0), mn1 = fmaxf(m1, mx1);
            float c0 = exp2f(m0 - mn0), c1 = exp2f(m1 - mn1);
            m0 = mn0; m1 = mn1;
            float sum0 = 0.f, sum1 = 0.f;
#pragma unroll
            for (int j = 0; j < 16; j++) {
                s[j][0] = exp2f(s[j][0] - m0);
                s[j][1] = exp2f(s[j][1] - m0);
                s[j][2] = exp2f(s[j][2] - m1);
                s[j][3] = exp2f(s[j][3] - m1);
                sum0 += s[j][0] + s[j][1];
                sum1 += s[j][2] + s[j][3];
            }
            sum0 += __shfl_xor_sync(0xffffffffu, sum0, 1);
            sum0 += __shfl_xor_sync(0xffffffffu, sum0, 2);
            sum1 += __shfl_xor_sync(0xffffffffu, sum1, 1);
            sum1 += __shfl_xor_sync(0xffffffffu, sum1, 2);
            l0 = l0 * c0 + sum0;
            l1 = l1 * c1 + sum1;

#pragma unroll
            for (int j = 0; j < 16; j++) {
                o[j][0] *= c0; o[j][1] *= c0;
                o[j][2] *= c1; o[j][3] *= c1;
            }

            // stage P (warp-private slab)
            {
                __half* p0 = Ps + (w * 16 + g) * LDP;
                __half* p1 = p0 + 8 * LDP;
#pragma unroll
                for (int j = 0; j < 16; j++) {
                    *(uint32_t*)(p0 + j * 8 + 2 * t) = h2pack(s[j][0], s[j][1]);
                    *(uint32_t*)(p1 + j * 8 + 2 * t) = h2pack(s[j][2], s[j][3]);
                }
            }
            __syncwarp();

            // O += P @ V (V transposed)
#pragma unroll
            for (int k16 = 0; k16 < 8; k16++) {
                const __half* pb = Ps + (w * 16 + g) * LDP + k16 * 16;
                uint32_t a[4];
                a[0] = *(const uint32_t*)(pb + 2 * t);
                a[1] = *(const uint32_t*)(pb + 8 * LDP + 2 * t);
                a[2] = *(const uint32_t*)(pb + 2 * t + 8);
                a[3] = *(const uint32_t*)(pb + 8 * LDP + 2 * t + 8);
#pragma unroll
                for (int j = 0; j < 16; j++) {
                    const __half* vb = Vcur + (j * 8 + g) * LDVT + k16 * 16;
                    uint32_t b[2];
                    b[0] = *(const uint32_t*)(vb + 2 * t);
                    b[1] = *(const uint32_t*)(vb + 2 * t + 8);
                    mma_f16(o[j], a, b);
                }
            }
        }

        // normalize + store fp16
        float inv0 = 1.f / l0, inv1 = 1.f / l1;
#pragma unroll
        for (int j = 0; j < 16; j++) {
            __half* a0 = g_att + (size_t)row0g * HID + head * DH + j * 8 + 2 * t;
            __half* a1 = a0 + 8 * HID;
            *(uint32_t*)a0 = h2pack(o[j][0] * inv0, o[j][1] * inv0);
            *(uint32_t*)a1 = h2pack(o[j][2] * inv1, o[j][3] * inv1);
        }
        __syncthreads();   // protect smem before next item's loads
    }
}

// ---------------------------------------------------------------------------
extern "C" void kernel_launch(void* const* d_in, const int* in_sizes, int n_in,
                              void* d_out, int out_size)
{
    const float* x      = (const float*)d_in[0];
    const float* Wq     = (const float*)d_in[1];
    const float* bq     = (const float*)d_in[2];
    const float* Wk     = (const float*)d_in[3];
    const float* bk     = (const float*)d_in[4];
    const float* Wv     = (const float*)d_in[5];
    const float* bv     = (const float*)d_in[6];
    const float* Wo     = (const float*)d_in[7];
    const float* k_hist = (const float*)d_in[8];
    const float* v_hist = (const float*)d_in[9];
    const float* fcos   = (const float*)d_in[10];
    const float* fsin   = (const float*)d_in[11];
    float* out = (float*)d_out;

    cudaFuncSetAttribute(attn_kernel,
                         cudaFuncAttributeMaxDynamicSharedMemorySize, ATTN_SMEM);
    cudaFuncSetAttribute(gemm_qkv_kernel,
                         cudaFuncAttributeMaxDynamicSharedMemorySize, GEMM_SMEM);
    cudaFuncSetAttribute(gemm_wo_kernel,
                         cudaFuncAttributeMaxDynamicSharedMemorySize, GEMM_SMEM);

    // fp32 -> fp16 copies (weights/v transposed); reset work queue
    cvt_kernel<<<2368, 256>>>(x, Wq, Wk, Wv, Wo, k_hist, v_hist);

    // fused QKV projection (fp16 mma)
    gemm_qkv_kernel<<<dim3(16, 16), 256, GEMM_SMEM>>>(bq, bk, bv);

    // RoPE
    rope_kernel<<<Q_LEN * 14, 64>>>(fcos, fsin);

    // attention (persistent, LPT queue, KTILE=128, single barrier/tile)
    attn_kernel<<<148, 256, ATTN_SMEM>>>();

    // output projection (fp32 out)
    gemm_wo_kernel<<<dim3(HID / 128, Q_LEN / 128), 256, GEMM_SMEM>>>(out);
}